// round 12
// baseline (speedup 1.0000x reference)
#include <cuda_runtime.h>

// ---------------- problem constants ----------------
#define NN      1536
#define NE      49152
#define EMB     32
#define SLOPE   0.2f
#define CAP     96             // bucket slots per node (P(deg>96) ~ 4e-20)
#define NB_NODE 192            // 192 node blocks * 8 warps = 1536 nodes
#define NB_EDGE 192            // 192 edge blocks * 256 edges = 49152

// ---------------- device scratch (allocation-free, replay-safe) ----------
__device__ float  g_tar   [NN * 4];        // float4 per node
__device__ float  g_nbr   [NN * 4];        // float4 per node
__device__ float  g_nbrupd[NN * EMB];
__device__ int    g_deg   [NN];            // zeroed at load; k_main resets each run
__device__ float4 g_escB  [NN * CAP];      // {s0,s1,s2, dst-as-int-bits}
__device__ float  g_updB  [NN * CAP * EMB];

__device__ __forceinline__ float leaky(float x) { return fmaxf(x, SLOPE * x); }

// packed f32x2 fma: acc.{lo,hi} += a.{lo,hi} * b.{lo,hi}
__device__ __forceinline__ void fma_f32x2(unsigned long long& acc,
                                          unsigned long long a,
                                          unsigned long long b) {
    asm("fma.rn.f32x2 %0, %1, %2, %0;" : "+l"(acc) : "l"(a), "l"(b));
}

// ================= K1: fused node + edge preprocessing ===================
__global__ __launch_bounds__(256) void k_prep(
    const float* __restrict__ node_f,
    const float* __restrict__ edge_attr,
    const float* __restrict__ edge_type,
    const float* __restrict__ W_veh,
    const float* __restrict__ W_ped,
    const float* __restrict__ W_ea,
    const float* __restrict__ W_et,
    const float* __restrict__ W_att,
    const float* __restrict__ W_upd,
    const int*   __restrict__ src,
    const int*   __restrict__ dst,
    const unsigned int* __restrict__ veh_raw,
    const unsigned int* __restrict__ ped_raw)
{
    __shared__ __align__(16) float sW[3 * 1024 + 384];
    int tid = threadIdx.x, lane = tid & 31, w = tid >> 5;

    if (blockIdx.x < NB_NODE) {
        // ---------- node part: warp per node (8 per block) ----------
        __shared__ int s_notInt, s_notF32;
        if (tid == 0) { s_notInt = 0; s_notF32 = 0; }
        __syncthreads();
        for (int idx = tid; idx < 384; idx += 256) {   // dtype sniff (min buf = 384 words)
            unsigned int x = veh_raw[idx];
            if (!(x == 0u || x == 1u))          atomicOr(&s_notInt, 1);
            if (!(x == 0u || x == 0x3F800000u)) atomicOr(&s_notF32, 1);
        }
        float* sWv  = sW;          // [c][o]
        float* sWp  = sW + 1024;
        float* sWun = sW + 2048;   // Wu_n [c][o]
        float* sWatt= sW + 3072;   // [h][128]
        for (int idx = tid; idx < 1024; idx += 256) {
            int o = idx >> 5, c = idx & 31;
            sWv [c * 32 + o] = W_veh[idx];
            sWp [c * 32 + o] = W_ped[idx];
            sWun[c * 32 + o] = W_upd[o * 64 + 32 + c];
        }
        for (int idx = tid; idx < 384; idx += 256) sWatt[idx] = W_att[idx];
        __syncthreads();
        int dtype = (!s_notInt) ? 0 : ((!s_notF32) ? 1 : 2);  // 0=i32,1=f32,2=u8

        int i = blockIdx.x * 8 + w;
        float f = node_f[i * 32 + lane];
        int v, p;
        if (dtype == 0)      { v = ((const int*)  veh_raw)[i] != 0;   p = ((const int*)  ped_raw)[i] != 0; }
        else if (dtype == 1) { v = ((const float*)veh_raw)[i] != 0.f; p = ((const float*)ped_raw)[i] != 0.f; }
        else                 { v = ((const unsigned char*)veh_raw)[i] != 0;
                               p = ((const unsigned char*)ped_raw)[i] != 0; }

        const float* Wt = p ? sWp : sWv;
        float acc = 0.f;
        #pragma unroll
        for (int c = 0; c < 32; c++)
            acc += __shfl_sync(0xffffffffu, f, c) * Wt[c * 32 + lane];
        float emb = (p || v) ? acc : 0.f;
        emb = leaky(emb);

        float t0 = emb * sWatt[lane],      t1 = emb * sWatt[128 + lane], t2 = emb * sWatt[256 + lane];
        float b0 = emb * sWatt[96 + lane], b1 = emb * sWatt[224 + lane], b2 = emb * sWatt[352 + lane];
        #pragma unroll
        for (int off = 16; off; off >>= 1) {
            t0 += __shfl_xor_sync(0xffffffffu, t0, off);
            t1 += __shfl_xor_sync(0xffffffffu, t1, off);
            t2 += __shfl_xor_sync(0xffffffffu, t2, off);
            b0 += __shfl_xor_sync(0xffffffffu, b0, off);
            b1 += __shfl_xor_sync(0xffffffffu, b1, off);
            b2 += __shfl_xor_sync(0xffffffffu, b2, off);
        }
        if (lane == 0) {
            ((float4*)g_tar)[i] = make_float4(t0, t1, t2, 0.f);
            ((float4*)g_nbr)[i] = make_float4(b0, b1, b2, 0.f);
        }
        float u = 0.f;
        #pragma unroll
        for (int c = 0; c < 32; c++)
            u += __shfl_sync(0xffffffffu, emb, c) * sWun[c * 32 + lane];
        g_nbrupd[i * 32 + lane] = u;
    } else {
        // ---------- edge part: thread = edge, packed f32x2 matvec ----------
        float4* sEA  = (float4*)sW;          // {wA0,wA1,wT0,wT1}[c]
        float4* sScA = (float4*)sW + 32;     // We_h[32+c]  (embA coeffs)
        float4* sScT = (float4*)sW + 64;     // We_h[64+c]  (embT coeffs)
        float2* sWuP = (float2*)((float4*)sW + 96);  // [c][o2]: (Wu[2o2][c], Wu[2o2+1][c])
        if (tid < 32) {
            sEA [tid] = make_float4(W_ea[tid * 2], W_ea[tid * 2 + 1],
                                    W_et[tid * 2], W_et[tid * 2 + 1]);
            sScA[tid] = make_float4(W_att[32 + tid], W_att[128 + 32 + tid], W_att[256 + 32 + tid], 0.f);
            sScT[tid] = make_float4(W_att[64 + tid], W_att[128 + 64 + tid], W_att[256 + 64 + tid], 0.f);
        }
        // Wu_e interleaved: sWuP[c*16 + o2] = (Wu[2o2][c], Wu[2o2+1][c]); 512 float2
        for (int idx = tid; idx < 512; idx += 256) {
            int c = idx >> 4, o2 = idx & 15;
            sWuP[idx] = make_float2(W_upd[(2 * o2) * 64 + c], W_upd[(2 * o2 + 1) * 64 + c]);
        }
        __syncthreads();

        int e = (blockIdx.x - NB_NODE) * 256 + tid;
        float2 ea = ((const float2*)edge_attr)[e];
        float2 et = ((const float2*)edge_type)[e];
        int sn = src[e], dn = dst[e];

        float embA[32];
        float s0 = 0.f, s1 = 0.f, s2 = 0.f;
        #pragma unroll
        for (int c = 0; c < 32; c++) {
            float4 wa = sEA[c];
            float a = leaky(wa.x * ea.x + wa.y * ea.y);
            float t = leaky(wa.z * et.x + wa.w * et.y);
            embA[c] = a;
            float4 pa = sScA[c], pt = sScT[c];
            s0 += a * pa.x + t * pt.x;
            s1 += a * pa.y + t * pt.y;
            s2 += a * pa.z + t * pt.z;
        }

        int pos = atomicAdd(&g_deg[sn], 1);   // latency hidden by matvec below

        // eupd = Wu_e * embA, two output channels per packed f32x2 accumulator
        unsigned long long acc[16];
        #pragma unroll
        for (int m = 0; m < 16; m++) acc[m] = 0ull;   // (0.f, 0.f)
        #pragma unroll
        for (int c = 0; c < 32; c++) {
            unsigned long long dup;
            asm("mov.b64 %0, {%1, %1};" : "=l"(dup) : "f"(embA[c]));
            const ulonglong2* row = (const ulonglong2*)(sWuP + c * 16);
            #pragma unroll
            for (int m = 0; m < 8; m++) {
                ulonglong2 wq = row[m];          // LDS.128 = 2 packed weight pairs
                fma_f32x2(acc[2 * m],     wq.x, dup);
                fma_f32x2(acc[2 * m + 1], wq.y, dup);
            }
        }

        if (pos < CAP) {
            int slot = sn * CAP + pos;
            g_escB[slot] = make_float4(s0, s1, s2, __int_as_float(dn));
            float4* up = (float4*)(g_updB + (size_t)slot * 32);
            #pragma unroll
            for (int q = 0; q < 8; q++) {
                float2 lo = *(float2*)&acc[2 * q];       // (out[4q],   out[4q+1])
                float2 hi = *(float2*)&acc[2 * q + 1];   // (out[4q+2], out[4q+3])
                up[q] = make_float4(lo.x, lo.y, hi.x, hi.y);
            }
        }
    }
}

// ================= K2: block-per-node attention + aggregation ==============
// (R7 verbatim — the 23.0us config)
__global__ __launch_bounds__(128) void k_main(float* __restrict__ out) {
    __shared__ int   sDst[CAP];
    __shared__ float sAtt[CAP * 3];
    __shared__ int   sHash[256];
    __shared__ int   sPm [32], sPk[32];
    __shared__ int   sNp;
    __shared__ float sSum[12];
    __shared__ float sPart[12 * 32];

    int i = blockIdx.x;
    int tid = threadIdx.x, lane = tid & 31, w = tid >> 5;

    int d = min(g_deg[i], CAP);
    float4 ti = ((const float4*)g_tar)[i];   // prefetch (broadcast)

    if (d == 0) {
        float acc = 0.f;
        for (int j = w; j < NN; j += 4) acc += leaky(g_nbrupd[j * 32 + lane]);
        sPart[w * 32 + lane] = acc;
        __syncthreads();
        if (tid < 96) {
            int o = tid & 31;
            out[i * 96 + tid] = (sPart[o] + sPart[32 + o] + sPart[64 + o] + sPart[96 + o]) * (1.f / NN);
        }
        return;
    }

    sHash[tid] = -1; sHash[tid + 128] = -1;
    if (tid == 0) sNp = 0;

    // thread -> edge mapping (spread across warps)
    int grp = tid & 3;
    int k = (tid >> 2) + (grp << 5);
    bool act = (grp < 3) && (k < d);

    // pass 1: load edge record, store raw scores, issue nbr gather early
    int dk = 0;
    float4 nb = make_float4(0.f, 0.f, 0.f, 0.f);
    if (act) {
        float4 sc = g_escB[i * CAP + k];
        dk = __float_as_int(sc.w);
        sDst[k] = dk;
        sAtt[k * 3]     = sc.x;
        sAtt[k * 3 + 1] = sc.y;
        sAtt[k * 3 + 2] = sc.z;
        nb = ((const float4*)g_nbr)[dk];   // latency overlapped with dedupe
    }
    __syncthreads();
    if (tid == 0) g_deg[i] = 0;   // reset for next graph replay (reads done)

    // pass 2: hash dedupe; dupes merge scores into root, zero own, record pair
    int leader = k;
    if (act) {
        unsigned h = ((unsigned)dk * 2654435761u) >> 24;
        while (true) {
            int old = atomicCAS(&sHash[h], -1, k);
            if (old == -1) break;                          // I'm the group root
            if (sDst[old] == dk) { leader = old; break; }  // found root
            h = (h + 1) & 255;
        }
        if (leader != k) {
            atomicAdd(&sAtt[leader * 3 + 0], sAtt[k * 3 + 0]);
            atomicAdd(&sAtt[leader * 3 + 1], sAtt[k * 3 + 1]);
            atomicAdd(&sAtt[leader * 3 + 2], sAtt[k * 3 + 2]);
            sAtt[k * 3] = 0.f; sAtt[k * 3 + 1] = 0.f; sAtt[k * 3 + 2] = 0.f;
            int p = atomicAdd(&sNp, 1);
            if (p < 32) { sPm[p] = leader; sPk[p] = k; }
        }
    }
    __syncthreads();

    // merge dupe upd-rows into root rows in global (rare; hidden behind exp pass)
    float* updRowG = g_updB + (size_t)i * CAP * 32;
    int np = min(sNp, 32);
    for (int p = w; p < np; p += 4) {
        float v = updRowG[sPk[p] * 32 + lane];
        atomicAdd(&updRowG[sPm[p] * 32 + lane], v);
    }

    // pass 3: finalize + exp (roots); dupes/inactive contribute 0
    float e0 = 0.f, e1 = 0.f, e2 = 0.f;
    if (act && leader == k) {
        e0 = __expf(leaky(ti.x + sAtt[k * 3]     + nb.x));
        e1 = __expf(leaky(ti.y + sAtt[k * 3 + 1] + nb.y));
        e2 = __expf(leaky(ti.z + sAtt[k * 3 + 2] + nb.z));
        sAtt[k * 3] = e0; sAtt[k * 3 + 1] = e1; sAtt[k * 3 + 2] = e2;
    } else if (act) {
        sAtt[k * 3] = 0.f; sAtt[k * 3 + 1] = 0.f; sAtt[k * 3 + 2] = 0.f;
    }
    float S0 = e0, S1 = e1, S2 = e2;
    #pragma unroll
    for (int off = 16; off; off >>= 1) {
        S0 += __shfl_xor_sync(0xffffffffu, S0, off);
        S1 += __shfl_xor_sync(0xffffffffu, S1, off);
        S2 += __shfl_xor_sync(0xffffffffu, S2, off);
    }
    if (lane == 0) { sSum[w * 3] = S0; sSum[w * 3 + 1] = S1; sSum[w * 3 + 2] = S2; }
    __syncthreads();   // also publishes the global upd-row merges to the block
    float inv0 = 1.f / (sSum[0] + sSum[3] + sSum[6] + sSum[9]);
    float inv1 = 1.f / (sSum[1] + sSum[4] + sSum[7] + sSum[10]);
    float inv2 = 1.f / (sSum[2] + sSum[5] + sSum[8] + sSum[11]);

    // phase B: dense aggregation over ALL d slots (dupes have weight 0)
    float a0 = 0.f, a1 = 0.f, a2 = 0.f;
    #pragma unroll 4
    for (int j = w; j < d; j += 4) {
        float w0 = sAtt[j * 3], w1 = sAtt[j * 3 + 1], w2 = sAtt[j * 3 + 2];
        float v = leaky(updRowG[j * 32 + lane] + g_nbrupd[sDst[j] * 32 + lane]);
        a0 += w0 * v; a1 += w1 * v; a2 += w2 * v;
    }
    sPart[(w * 3 + 0) * 32 + lane] = a0;
    sPart[(w * 3 + 1) * 32 + lane] = a1;
    sPart[(w * 3 + 2) * 32 + lane] = a2;
    __syncthreads();
    if (tid < 96) {
        int h = tid / 32, o = tid % 32;
        float inv = (h == 0) ? inv0 : ((h == 1) ? inv1 : inv2);
        out[i * 96 + h * 32 + o] =
            (sPart[(0 + h) * 32 + o] + sPart[(3 + h) * 32 + o]
           + sPart[(6 + h) * 32 + o] + sPart[(9 + h) * 32 + o]) * inv;
    }
}

// ---------------- launch ----------------
extern "C" void kernel_launch(void* const* d_in, const int* in_sizes, int n_in,
                              void* d_out, int out_size) {
    const float* node_f    = (const float*)d_in[0];
    const float* edge_attr = (const float*)d_in[1];
    const float* edge_type = (const float*)d_in[2];
    const float* W_veh     = (const float*)d_in[3];
    const float* W_ped     = (const float*)d_in[4];
    const float* W_ea      = (const float*)d_in[5];
    const float* W_et      = (const float*)d_in[6];
    const float* W_att     = (const float*)d_in[7];
    const float* W_upd     = (const float*)d_in[8];
    const int*   edge_index= (const int*)  d_in[9];
    const unsigned int* veh = (const unsigned int*)d_in[10];
    const unsigned int* ped = (const unsigned int*)d_in[11];

    const int* src = edge_index;        // edge_index[0, :]
    const int* dst = edge_index + NE;   // edge_index[1, :]
    float* out = (float*)d_out;

    k_prep<<<NB_NODE + NB_EDGE, 256>>>(node_f, edge_attr, edge_type,
                                       W_veh, W_ped, W_ea, W_et, W_att, W_upd,
                                       src, dst, veh, ped);
    k_main<<<NN, 128>>>(out);
}